// round 11
// baseline (speedup 1.0000x reference)
#include <cuda_runtime.h>
#include <cuda_fp16.h>
#include <stdint.h>

// Problem constants (fixed by dataset)
#define NL    4
#define Bz    64
#define Hd    512
#define Tmax  256
#define NCTA  128
#define NTHR  256

#define RSTRIDE 66                       // padded row stride for reduction buf
#define SMEM_W   (4*64*32*16)            // 131072 B: A-fragments, 4 layers x 64 ktiles
#define SMEM_RED (4*16*RSTRIDE*4)        // 16896 B
#define SMEM_TOT (SMEM_W + SMEM_RED)

// ---------------- persistent device state (no allocation allowed) ----------------
// Activations packed in B-fragment order, single fp16, 8B/lane = {b0,b1}
// plane = [32 ktiles][8 ntiles][32 lanes][4 halves] = 32768 halves
__device__ __align__(16) __half g_Xin [2][NL][32768];  // input to layer l, parity p
__device__ __align__(16) __half g_Hrec[2][NL][32768];  // recurrent h of layer l, parity p
// One arrival flag per CTA, padded to a 32B sector. Monotonic across graph
// replays: each CTA reads its own flag at entry (base S, uniform since all
// launches complete), targets are S+k. No reset, no race.
__device__ unsigned g_flags[NCTA * 8];

// fast-math activations (MUFU-based, ~1e-6 rel err)
__device__ __forceinline__ float sigm(float x) {
    return __fdividef(1.0f, 1.0f + __expf(-x));
}
__device__ __forceinline__ float tanhfast(float x) {
    return __fdividef(2.0f, 1.0f + __expf(-2.0f * x)) - 1.0f;
}

// offset of X element (k,n) inside a packed plane (single fp16)
__device__ __forceinline__ int xoff(int k, int n) {
    int kt = k >> 4, kr = k & 15, nt = n >> 3, nc = n & 7;
    int lane = nc * 4 + ((kr >> 1) & 3);
    return ((kt * 8 + nt) * 32 + lane) * 4 + ((kr >> 3) * 2 + (kr & 1));
}

__device__ __forceinline__ void mma16816(float* c,
                                         unsigned a0, unsigned a1, unsigned a2, unsigned a3,
                                         unsigned b0, unsigned b1) {
    asm volatile(
        "mma.sync.aligned.m16n8k16.row.col.f32.f16.f16.f32 "
        "{%0,%1,%2,%3}, {%4,%5,%6,%7}, {%8,%9}, {%0,%1,%2,%3};\n"
        : "+f"(c[0]), "+f"(c[1]), "+f"(c[2]), "+f"(c[3])
        : "r"(a0), "r"(a1), "r"(a2), "r"(a3), "r"(b0), "r"(b1));
}

// warp-parallel barrier poll: lane checks 4 CTAs' flags, wrap-safe compare
__device__ __forceinline__ void poll_flags(unsigned tgt, int lane) {
    volatile unsigned* f = g_flags;
    for (;;) {
        bool ok = true;
#pragma unroll
        for (int i = 0; i < 4; i++)
            ok &= ((int)(f[(lane + 32 * i) * 8] - tgt) >= 0);
        if (__all_sync(0xffffffffu, ok)) break;
    }
}

// load 8 ktiles x 4 ntiles of B fragments (32 LDG.64, max MLP)
__device__ __forceinline__ void load_frags(uint2 bb[8][4], const uint2* __restrict__ Bp,
                                           int kt0, int nt0, int lane) {
#pragma unroll
    for (int q = 0; q < 8; q++)
#pragma unroll
        for (int n = 0; n < 4; n++)
            bb[q][n] = __ldcg(Bp + (((kt0 + q) * 8 + nt0 + n) * 32 + lane));
}

// 32 MMAs consuming preloaded fragments; sA pre-offset to (layer,ktile,lane)
__device__ __forceinline__ void mma_frags(float acc[4][4], const uint4* __restrict__ sA,
                                          uint2 bb[8][4]) {
#pragma unroll
    for (int q = 0; q < 8; q++) {
        uint4 a = sA[q * 32];
#pragma unroll
        for (int n = 0; n < 4; n++)
            mma16816(acc[n], a.x, a.y, a.z, a.w, bb[q][n].x, bb[q][n].y);
    }
}

// ---------------- single persistent kernel ----------------
// CTA owns 16 gate rows (4 units x 4 gates). Warp w: kquad = w&3 (8 ktiles per
// half), nhalf = w>>2 (4 ntiles). Hrec loads for round r+1 issue before the
// epilogue (latency hidden); Hrec MMAs run after arrive(r).
__global__ void __launch_bounds__(NTHR, 1) lstm_all(
    const float* __restrict__ y,
    const float* __restrict__ h0,
    const float* __restrict__ c0,
    const float* __restrict__ Wih,
    const float* __restrict__ Whh,
    const float* __restrict__ bih,
    const float* __restrict__ bhh,
    const int*   __restrict__ seqp,
    float*       __restrict__ out)
{
    extern __shared__ char sm[];
    __half* sW  = (__half*)sm;            // [4][64][32] uint4 A-fragments
    float*  red = (float*)(sm + SMEM_W);  // [4 kquads][16 rows][RSTRIDE]

    const int tid  = threadIdx.x;
    const int cta  = blockIdx.x;
    const int w    = tid >> 5;
    const int lane = tid & 31;
    const int u0   = cta * 4;

    // base flag value (only this CTA writes its flag -> uniform across CTAs)
    const unsigned S = *(volatile unsigned*)&g_flags[cta * 8];

    // ---- prologue A: pack this CTA's weights straight into smem (fp16 frags) ----
#pragma unroll 4
    for (int i = 0; i < 32; i++) {
        int idx = i * NTHR + tid;                 // 0..8191 = ((l*64+kt)*32+ln)
        int ln = idx & 31, kt = (idx >> 5) & 63, l = idx >> 11;
        const float* W = ((kt < 32) ? Wih : Whh) + (size_t)l * 4 * Hd * Hd;
        int kb = (kt & 31) * 16 + (ln & 3) * 2;
        __half h8[8];
#pragma unroll
        for (int areg = 0; areg < 4; areg++) {
            int r = (ln >> 2) + (areg & 1) * 8;   // A row 0..15
            int grow = (r & 3) * Hd + u0 + (r >> 2);
            float2 v = *(const float2*)&W[(size_t)grow * Hd + kb + (areg >> 1) * 8];
            h8[areg * 2 + 0] = __float2half_rn(v.x);
            h8[areg * 2 + 1] = __float2half_rn(v.y);
        }
        *(uint4*)&sW[(size_t)idx * 8] = *(uint4*)h8;
    }

    // ---- prologue B: pack initial state (grid-strided) ----
    for (int i = cta * NTHR + tid; i < (NL + 1) * Hd * Bz; i += NCTA * NTHR) {
        int u = (i & 32767) >> 6, b = i & 63;
        if (i < Hd * Bz)
            g_Xin[0][0][xoff(u, b)] = __float2half_rn(y[b * Hd + u]);
        else {
            int l = (i >> 15) - 1;
            g_Hrec[0][l][xoff(u, b)] =
                __float2half_rn(h0[(size_t)l * Bz * Hd + b * Hd + u]);
        }
    }

    // epilogue mapping: thread -> (unit j, batch c)
    const int j = tid >> 6;
    const int c = tid & 63;
    const int u = u0 + j;
    const int xo = xoff(u, c);

    float cst[NL];
#pragma unroll
    for (int l = 0; l < NL; l++)
        cst[l] = c0[(size_t)l * Bz * Hd + c * Hd + u];

    float bias[NL][4];
#pragma unroll
    for (int l = 0; l < NL; l++)
#pragma unroll
        for (int g = 0; g < 4; g++)
            bias[l][g] = bih[l * 4 * Hd + g * Hd + u] + bhh[l * 4 * Hd + g * Hd + u];

    int T = Tmax;
    if (seqp) { int tv = *seqp; if (tv > 0 && tv <= Tmax) T = tv; }
    const int R = NL * T;

    // ---- prologue grid barrier (arrival k=1) ----
    __threadfence();
    __syncthreads();
    if (tid == 0) __stcg(&g_flags[cta * 8], S + 1);
    if (w == 0) poll_flags(S + 1, lane);
    __syncthreads();

    // warp roles
    const int kq  = w & 3;          // K quadrant (8 ktiles per half)
    const int nt0 = (w >> 2) * 4;   // first ntile of this warp's N half
    const int kt0 = kq * 8;         // plane-local first ktile
    const uint4* sA0 = (const uint4*)sW;

    uint2 bb[8][4];
    float acc[4][4];
#pragma unroll
    for (int n = 0; n < 4; n++)
#pragma unroll
        for (int q = 0; q < 4; q++) acc[n][q] = 0.f;

    // Hrec half for round 0 (t=0, l=0, p=0)
    load_frags(bb, (const uint2*)&g_Hrec[0][0][0], kt0, nt0, lane);
    mma_frags(acc, sA0 + (0 * 64 + 32 + kt0) * 32 + lane, bb);

    for (int r = 0; r < R; r++) {
        const int t = r >> 2, l = r & 3, p = t & 1;

        // wait(r-1): Xin plane for round r ready (prologue barrier covers r=0)
        if (r > 0) {
            if (w == 0) poll_flags(S + 1 + r, lane);
            __syncthreads();
        }

        // Xin half of round r (critical path)
        load_frags(bb, (const uint2*)&g_Xin[p][l][0], kt0, nt0, lane);
        mma_frags(acc, sA0 + (l * 64 + kt0) * 32 + lane, bb);

        // cross-warp K reduction (4-way) via smem
        {
            int gid = lane >> 2, tig = lane & 3;
#pragma unroll
            for (int n = 0; n < 4; n++) {
                int col = (nt0 + n) * 8 + tig * 2;
                *(float2*)&red[(kq * 16 + gid)     * RSTRIDE + col] =
                    make_float2(acc[n][0], acc[n][1]);
                *(float2*)&red[(kq * 16 + gid + 8) * RSTRIDE + col] =
                    make_float2(acc[n][2], acc[n][3]);
            }
        }
        __syncthreads();

        // early Hrec(r+1) fragment loads — latency hides under epilogue
        const int r2 = r + 1, l2 = r2 & 3, p2 = (r2 >> 2) & 1;
        if (r2 < R)
            load_frags(bb, (const uint2*)&g_Hrec[p2][l2][0], kt0, nt0, lane);

        float s0 = 0.f, s1 = 0.f, s2 = 0.f, s3 = 0.f;
#pragma unroll
        for (int kk = 0; kk < 4; kk++) {
            const float* rw = &red[(kk * 16 + j * 4) * RSTRIDE + c];
            s0 += rw[0];
            s1 += rw[RSTRIDE];
            s2 += rw[2 * RSTRIDE];
            s3 += rw[3 * RSTRIDE];
        }

        float iG = sigm(s0 + bias[l][0]);
        float fG = sigm(s1 + bias[l][1]);
        float gG = tanhfast(s2 + bias[l][2]);
        float oG = sigm(s3 + bias[l][3]);
        float cn = fG * cst[l] + iG * gG;
        cst[l] = cn;
        float hn = oG * tanhfast(cn);

        // publish h (single fp16): next-layer input slot + own recurrent slot
        {
            unsigned short hb = __half_as_ushort(__float2half_rn(hn));
            __half* xdst = (l < NL - 1) ? &g_Xin[p][l + 1][0] : &g_Xin[p ^ 1][0][0];
            __stcg((unsigned short*)&xdst[xo], hb);
            __stcg((unsigned short*)&g_Hrec[p ^ 1][l][xo], hb);
        }
        if (l == NL - 1)
            out[((size_t)c * T + t) * Hd + u] = hn;   // out[b][t][u]

        // arrive(r): publishes visible, then parallel flag store (no atomics)
        __threadfence();
        __syncthreads();           // also guards red reuse
        if (tid == 0) __stcg(&g_flags[cta * 8], S + 2 + r);

        // Hrec MMAs for round r+1 (fragments already in registers)
        if (r2 < R) {
#pragma unroll
            for (int n = 0; n < 4; n++)
#pragma unroll
                for (int q = 0; q < 4; q++) acc[n][q] = 0.f;
            mma_frags(acc, sA0 + (l2 * 64 + 32 + kt0) * 32 + lane, bb);
        }
    }
}

extern "C" void kernel_launch(void* const* d_in, const int* in_sizes, int n_in,
                              void* d_out, int out_size) {
    const float* y   = (const float*)d_in[0];
    const float* h0  = (const float*)d_in[1];
    const float* c0  = (const float*)d_in[2];
    const float* Wih = (const float*)d_in[3];
    const float* Whh = (const float*)d_in[4];
    const float* bih = (const float*)d_in[5];
    const float* bhh = (const float*)d_in[6];
    const int*   sl  = (n_in >= 8) ? (const int*)d_in[7] : nullptr;
    float* out = (float*)d_out;
    (void)in_sizes; (void)out_size;

    cudaFuncSetAttribute(lstm_all, cudaFuncAttributeMaxDynamicSharedMemorySize, SMEM_TOT);
    lstm_all<<<NCTA, NTHR, SMEM_TOT>>>(y, h0, c0, Wih, Whh, bih, bhh, sl, out);
}

// round 12
// speedup vs baseline: 1.3249x; 1.3249x over previous
#include <cuda_runtime.h>
#include <cuda_fp16.h>
#include <stdint.h>

// Problem constants (fixed by dataset)
#define NL    4
#define Bz    64
#define Hd    512
#define Tmax  256
#define NCTA  128
#define NTHR  256

#define RSTRIDE 66                       // padded row stride for reduction buf
#define SMEM_W   (4*64*32*16)            // 131072 B: A-fragments, 4 layers x 64 ktiles
#define SMEM_RED (4*16*RSTRIDE*4)        // 16896 B
#define SMEM_TOT (SMEM_W + SMEM_RED)

// ---------------- persistent device state (no allocation allowed) ----------------
// Activations packed in B-fragment order, single fp16, 8B/lane = {b0,b1}
// plane = [32 ktiles][8 ntiles][32 lanes][4 halves] = 32768 halves
__device__ __align__(16) __half g_Xin [2][NL][32768];  // input to layer l, parity p
__device__ __align__(16) __half g_Hrec[2][NL][32768];  // recurrent h of layer l, parity p
__device__ unsigned g_bar;                             // monotonic; self-reset at end

// fast-math activations (MUFU-based, ~1e-6 rel err)
__device__ __forceinline__ float sigm(float x) {
    return __fdividef(1.0f, 1.0f + __expf(-x));
}
__device__ __forceinline__ float tanhfast(float x) {
    return __fdividef(2.0f, 1.0f + __expf(-2.0f * x)) - 1.0f;
}

// release-ordered arrive: orders all prior stores (collected by __syncthreads)
// before the counter increment becomes visible. Replaces threadfence+atomicAdd.
__device__ __forceinline__ void arrive_release(unsigned* bar) {
    asm volatile("red.release.gpu.global.add.u32 [%0], 1;" :: "l"(bar) : "memory");
}

// offset of X element (k,n) inside a packed plane (single fp16)
__device__ __forceinline__ int xoff(int k, int n) {
    int kt = k >> 4, kr = k & 15, nt = n >> 3, nc = n & 7;
    int lane = nc * 4 + ((kr >> 1) & 3);
    return ((kt * 8 + nt) * 32 + lane) * 4 + ((kr >> 3) * 2 + (kr & 1));
}

__device__ __forceinline__ void mma16816(float* c,
                                         unsigned a0, unsigned a1, unsigned a2, unsigned a3,
                                         unsigned b0, unsigned b1) {
    asm volatile(
        "mma.sync.aligned.m16n8k16.row.col.f32.f16.f16.f32 "
        "{%0,%1,%2,%3}, {%4,%5,%6,%7}, {%8,%9}, {%0,%1,%2,%3};\n"
        : "+f"(c[0]), "+f"(c[1]), "+f"(c[2]), "+f"(c[3])
        : "r"(a0), "r"(a1), "r"(a2), "r"(a3), "r"(b0), "r"(b1));
}

// load 8 ktiles x 4 ntiles of B fragments (32 LDG.64, max MLP)
__device__ __forceinline__ void load_frags(uint2 bb[8][4], const uint2* __restrict__ Bp,
                                           int kt0, int nt0, int lane) {
#pragma unroll
    for (int q = 0; q < 8; q++)
#pragma unroll
        for (int n = 0; n < 4; n++)
            bb[q][n] = __ldcg(Bp + (((kt0 + q) * 8 + nt0 + n) * 32 + lane));
}

// 32 MMAs consuming preloaded fragments; sA pre-offset to (layer,ktile,lane)
__device__ __forceinline__ void mma_frags(float acc[4][4], const uint4* __restrict__ sA,
                                          uint2 bb[8][4]) {
#pragma unroll
    for (int q = 0; q < 8; q++) {
        uint4 a = sA[q * 32];
#pragma unroll
        for (int n = 0; n < 4; n++)
            mma16816(acc[n], a.x, a.y, a.z, a.w, bb[q][n].x, bb[q][n].y);
    }
}

// ---------------- single persistent kernel ----------------
// CTA owns 16 gate rows (4 units x 4 gates). Warp w: kquad = w&3 (8 ktiles per
// half), nhalf = w>>2 (4 ntiles). Hrec loads for round r+1 issue before the
// epilogue (latency hidden); Hrec MMAs run after arrive(r).
__global__ void __launch_bounds__(NTHR, 1) lstm_all(
    const float* __restrict__ y,
    const float* __restrict__ h0,
    const float* __restrict__ c0,
    const float* __restrict__ Wih,
    const float* __restrict__ Whh,
    const float* __restrict__ bih,
    const float* __restrict__ bhh,
    const int*   __restrict__ seqp,
    float*       __restrict__ out)
{
    extern __shared__ char sm[];
    __half* sW  = (__half*)sm;            // [4][64][32] uint4 A-fragments
    float*  red = (float*)(sm + SMEM_W);  // [4 kquads][16 rows][RSTRIDE]

    const int tid  = threadIdx.x;
    const int cta  = blockIdx.x;
    const int w    = tid >> 5;
    const int lane = tid & 31;
    const int u0   = cta * 4;

    // ---- prologue A: pack this CTA's weights straight into smem (fp16 frags) ----
#pragma unroll 4
    for (int i = 0; i < 32; i++) {
        int idx = i * NTHR + tid;                 // 0..8191 = ((l*64+kt)*32+ln)
        int ln = idx & 31, kt = (idx >> 5) & 63, l = idx >> 11;
        const float* W = ((kt < 32) ? Wih : Whh) + (size_t)l * 4 * Hd * Hd;
        int kb = (kt & 31) * 16 + (ln & 3) * 2;
        __half h8[8];
#pragma unroll
        for (int areg = 0; areg < 4; areg++) {
            int r = (ln >> 2) + (areg & 1) * 8;   // A row 0..15
            int grow = (r & 3) * Hd + u0 + (r >> 2);
            float2 v = *(const float2*)&W[(size_t)grow * Hd + kb + (areg >> 1) * 8];
            h8[areg * 2 + 0] = __float2half_rn(v.x);
            h8[areg * 2 + 1] = __float2half_rn(v.y);
        }
        *(uint4*)&sW[(size_t)idx * 8] = *(uint4*)h8;
    }

    // ---- prologue B: pack initial state (grid-strided) ----
    for (int i = cta * NTHR + tid; i < (NL + 1) * Hd * Bz; i += NCTA * NTHR) {
        int u = (i & 32767) >> 6, b = i & 63;
        if (i < Hd * Bz)
            g_Xin[0][0][xoff(u, b)] = __float2half_rn(y[b * Hd + u]);
        else {
            int l = (i >> 15) - 1;
            g_Hrec[0][l][xoff(u, b)] =
                __float2half_rn(h0[(size_t)l * Bz * Hd + b * Hd + u]);
        }
    }

    // epilogue mapping: thread -> (unit j, batch c)
    const int j = tid >> 6;
    const int c = tid & 63;
    const int u = u0 + j;
    const int xo = xoff(u, c);

    float cst[NL];
#pragma unroll
    for (int l = 0; l < NL; l++)
        cst[l] = c0[(size_t)l * Bz * Hd + c * Hd + u];

    float bias[NL][4];
#pragma unroll
    for (int l = 0; l < NL; l++)
#pragma unroll
        for (int g = 0; g < 4; g++)
            bias[l][g] = bih[l * 4 * Hd + g * Hd + u] + bhh[l * 4 * Hd + g * Hd + u];

    int T = Tmax;
    if (seqp) { int tv = *seqp; if (tv > 0 && tv <= Tmax) T = tv; }
    const int R = NL * T;

    // ---- prologue grid barrier ----
    __syncthreads();
    if (tid == 0) {
        arrive_release(&g_bar);
        volatile unsigned* vb = &g_bar;
        while (*vb < NCTA) { }
    }
    __syncthreads();

    // warp roles
    const int kq  = w & 3;          // K quadrant (8 ktiles per half)
    const int nt0 = (w >> 2) * 4;   // first ntile of this warp's N half
    const int kt0 = kq * 8;         // plane-local first ktile
    const uint4* sA0 = (const uint4*)sW;

    uint2 bb[8][4];
    float acc[4][4];
#pragma unroll
    for (int n = 0; n < 4; n++)
#pragma unroll
        for (int q = 0; q < 4; q++) acc[n][q] = 0.f;

    // Hrec half for round 0 (t=0, l=0, p=0)
    load_frags(bb, (const uint2*)&g_Hrec[0][0][0], kt0, nt0, lane);
    mma_frags(acc, sA0 + (0 * 64 + 32 + kt0) * 32 + lane, bb);

    for (int r = 0; r < R; r++) {
        const int t = r >> 2, l = r & 3, p = t & 1;

        // wait(r-1): Xin plane for round r ready (prologue barrier covers r=0)
        if (r > 0) {
            if (tid == 0) {
                const unsigned target = (unsigned)(r + 1) * NCTA;
                volatile unsigned* vb = &g_bar;
                while (*vb < target) { }
            }
            __syncthreads();
        }

        // Xin half of round r (critical path)
        load_frags(bb, (const uint2*)&g_Xin[p][l][0], kt0, nt0, lane);
        mma_frags(acc, sA0 + (l * 64 + kt0) * 32 + lane, bb);

        // cross-warp K reduction (4-way) via smem
        {
            int gid = lane >> 2, tig = lane & 3;
#pragma unroll
            for (int n = 0; n < 4; n++) {
                int col = (nt0 + n) * 8 + tig * 2;
                *(float2*)&red[(kq * 16 + gid)     * RSTRIDE + col] =
                    make_float2(acc[n][0], acc[n][1]);
                *(float2*)&red[(kq * 16 + gid + 8) * RSTRIDE + col] =
                    make_float2(acc[n][2], acc[n][3]);
            }
        }
        __syncthreads();

        // early Hrec(r+1) fragment loads — latency hides under epilogue
        const int r2 = r + 1, l2 = r2 & 3, p2 = (r2 >> 2) & 1;
        if (r2 < R)
            load_frags(bb, (const uint2*)&g_Hrec[p2][l2][0], kt0, nt0, lane);

        float s0 = 0.f, s1 = 0.f, s2 = 0.f, s3 = 0.f;
#pragma unroll
        for (int kk = 0; kk < 4; kk++) {
            const float* rw = &red[(kk * 16 + j * 4) * RSTRIDE + c];
            s0 += rw[0];
            s1 += rw[RSTRIDE];
            s2 += rw[2 * RSTRIDE];
            s3 += rw[3 * RSTRIDE];
        }

        float iG = sigm(s0 + bias[l][0]);
        float fG = sigm(s1 + bias[l][1]);
        float gG = tanhfast(s2 + bias[l][2]);
        float oG = sigm(s3 + bias[l][3]);
        float cn = fG * cst[l] + iG * gG;
        cst[l] = cn;
        float hn = oG * tanhfast(cn);

        // publish h (single fp16): next-layer input slot + own recurrent slot
        {
            unsigned short hb = __half_as_ushort(__float2half_rn(hn));
            __half* xdst = (l < NL - 1) ? &g_Xin[p][l + 1][0] : &g_Xin[p ^ 1][0][0];
            __stcg((unsigned short*)&xdst[xo], hb);
            __stcg((unsigned short*)&g_Hrec[p ^ 1][l][xo], hb);
        }
        if (l == NL - 1)
            out[((size_t)c * T + t) * Hd + u] = hn;   // out[b][t][u]

        // arrive(r): syncthreads collects all threads' publishes; release-red
        // orders them before the counter increment. No separate membar.
        __syncthreads();           // also guards red reuse
        if (tid == 0) arrive_release(&g_bar);

        // Hrec MMAs for round r+1 (fragments already in registers)
        if (r2 < R) {
#pragma unroll
            for (int n = 0; n < 4; n++)
#pragma unroll
                for (int q = 0; q < 4; q++) acc[n][q] = 0.f;
            mma_frags(acc, sA0 + (l2 * 64 + 32 + kt0) * 32 + lane, bb);
        }
    }

    // self-reset barrier for next graph replay (deterministic state)
    if (cta == 0 && tid == 0) {
        volatile unsigned* vb = &g_bar;
        while (*vb < (unsigned)(R + 1) * NCTA) { }
        *vb = 0u;
    }
}

extern "C" void kernel_launch(void* const* d_in, const int* in_sizes, int n_in,
                              void* d_out, int out_size) {
    const float* y   = (const float*)d_in[0];
    const float* h0  = (const float*)d_in[1];
    const float* c0  = (const float*)d_in[2];
    const float* Wih = (const float*)d_in[3];
    const float* Whh = (const float*)d_in[4];
    const float* bih = (const float*)d_in[5];
    const float* bhh = (const float*)d_in[6];
    const int*   sl  = (n_in >= 8) ? (const int*)d_in[7] : nullptr;
    float* out = (float*)d_out;
    (void)in_sizes; (void)out_size;

    cudaFuncSetAttribute(lstm_all, cudaFuncAttributeMaxDynamicSharedMemorySize, SMEM_TOT);
    lstm_all<<<NCTA, NTHR, SMEM_TOT>>>(y, h0, c0, Wih, Whh, bih, bhh, sl, out);
}

// round 13
// speedup vs baseline: 1.3608x; 1.0271x over previous
#include <cuda_runtime.h>
#include <cuda_fp16.h>
#include <stdint.h>

// Problem constants (fixed by dataset)
#define NL    4
#define Bz    64
#define Hd    512
#define Tmax  256
#define NCTA  128
#define NTHR  256

#define RSTRIDE 66                       // padded row stride for reduction buf
#define SMEM_W   (4*64*32*16)            // 131072 B: A-fragments, 4 layers x 64 ktiles
#define SMEM_RED (4*16*RSTRIDE*4)        // 16896 B
#define SMEM_TOT (SMEM_W + SMEM_RED)

// ---------------- persistent device state (no allocation allowed) ----------------
// Activations packed in B-fragment order, single fp16, 8B/lane = {b0,b1}
// plane = [32 ktiles][8 ntiles][32 lanes][4 halves] = 32768 halves
__device__ __align__(16) __half g_Xin [2][NL][32768];  // input to layer l, parity p
__device__ __align__(16) __half g_Hrec[2][NL][32768];  // recurrent h of layer l, parity p
__device__ unsigned g_bar;                             // monotonic; self-reset at end

// fast-math activations (MUFU-based, ~1e-6 rel err)
__device__ __forceinline__ float sigm(float x) {
    return __fdividef(1.0f, 1.0f + __expf(-x));
}
__device__ __forceinline__ float tanhfast(float x) {
    return __fdividef(2.0f, 1.0f + __expf(-2.0f * x)) - 1.0f;
}

// release-ordered arrive: orders all prior stores (collected by __syncthreads)
// before the counter increment becomes visible.
__device__ __forceinline__ void arrive_release(unsigned* bar) {
    asm volatile("red.release.gpu.global.add.u32 [%0], 1;" :: "l"(bar) : "memory");
}

// throttled spin: a few hard polls, then back off so 128 pollers don't
// saturate the barrier's L2 line and delay the arriving atomics.
__device__ __forceinline__ void wait_ge(volatile unsigned* vb, unsigned target) {
    int spins = 0;
    while (*vb < target) {
        if (++spins > 4) __nanosleep(64);
    }
}

// offset of X element (k,n) inside a packed plane (single fp16)
__device__ __forceinline__ int xoff(int k, int n) {
    int kt = k >> 4, kr = k & 15, nt = n >> 3, nc = n & 7;
    int lane = nc * 4 + ((kr >> 1) & 3);
    return ((kt * 8 + nt) * 32 + lane) * 4 + ((kr >> 3) * 2 + (kr & 1));
}

__device__ __forceinline__ void mma16816(float* c,
                                         unsigned a0, unsigned a1, unsigned a2, unsigned a3,
                                         unsigned b0, unsigned b1) {
    asm volatile(
        "mma.sync.aligned.m16n8k16.row.col.f32.f16.f16.f32 "
        "{%0,%1,%2,%3}, {%4,%5,%6,%7}, {%8,%9}, {%0,%1,%2,%3};\n"
        : "+f"(c[0]), "+f"(c[1]), "+f"(c[2]), "+f"(c[3])
        : "r"(a0), "r"(a1), "r"(a2), "r"(a3), "r"(b0), "r"(b1));
}

// load 8 ktiles x 4 ntiles of B fragments (32 LDG.64, max MLP)
__device__ __forceinline__ void load_frags(uint2 bb[8][4], const uint2* __restrict__ Bp,
                                           int kt0, int nt0, int lane) {
#pragma unroll
    for (int q = 0; q < 8; q++)
#pragma unroll
        for (int n = 0; n < 4; n++)
            bb[q][n] = __ldcg(Bp + (((kt0 + q) * 8 + nt0 + n) * 32 + lane));
}

// preload 8 A-fragments (smem -> registers)
__device__ __forceinline__ void load_afrags(uint4 a[8], const uint4* __restrict__ sA) {
#pragma unroll
    for (int q = 0; q < 8; q++) a[q] = sA[q * 32];
}

// 32 MMAs from preloaded register A-fragments
__device__ __forceinline__ void mma_frags_reg(float acc[4][4], const uint4 a[8],
                                              uint2 bb[8][4]) {
#pragma unroll
    for (int q = 0; q < 8; q++)
#pragma unroll
        for (int n = 0; n < 4; n++)
            mma16816(acc[n], a[q].x, a[q].y, a[q].z, a[q].w, bb[q][n].x, bb[q][n].y);
}

// 32 MMAs reading A-fragments from smem (off-critical-path half)
__device__ __forceinline__ void mma_frags(float acc[4][4], const uint4* __restrict__ sA,
                                          uint2 bb[8][4]) {
#pragma unroll
    for (int q = 0; q < 8; q++) {
        uint4 a = sA[q * 32];
#pragma unroll
        for (int n = 0; n < 4; n++)
            mma16816(acc[n], a.x, a.y, a.z, a.w, bb[q][n].x, bb[q][n].y);
    }
}

// ---------------- single persistent kernel ----------------
// CTA owns 16 gate rows (4 units x 4 gates). Warp w: kquad = w&3 (8 ktiles per
// half), nhalf = w>>2 (4 ntiles). Hrec loads for round r+1 issue before the
// epilogue; Hrec MMAs run after arrive(r); Xin A-frags preloaded pre-wait.
__global__ void __launch_bounds__(NTHR, 1) lstm_all(
    const float* __restrict__ y,
    const float* __restrict__ h0,
    const float* __restrict__ c0,
    const float* __restrict__ Wih,
    const float* __restrict__ Whh,
    const float* __restrict__ bih,
    const float* __restrict__ bhh,
    const int*   __restrict__ seqp,
    float*       __restrict__ out)
{
    extern __shared__ char sm[];
    __half* sW  = (__half*)sm;            // [4][64][32] uint4 A-fragments
    float*  red = (float*)(sm + SMEM_W);  // [4 kquads][16 rows][RSTRIDE]

    const int tid  = threadIdx.x;
    const int cta  = blockIdx.x;
    const int w    = tid >> 5;
    const int lane = tid & 31;
    const int u0   = cta * 4;

    // ---- prologue A: pack this CTA's weights straight into smem (fp16 frags) ----
#pragma unroll 4
    for (int i = 0; i < 32; i++) {
        int idx = i * NTHR + tid;                 // 0..8191 = ((l*64+kt)*32+ln)
        int ln = idx & 31, kt = (idx >> 5) & 63, l = idx >> 11;
        const float* W = ((kt < 32) ? Wih : Whh) + (size_t)l * 4 * Hd * Hd;
        int kb = (kt & 31) * 16 + (ln & 3) * 2;
        __half h8[8];
#pragma unroll
        for (int areg = 0; areg < 4; areg++) {
            int r = (ln >> 2) + (areg & 1) * 8;   // A row 0..15
            int grow = (r & 3) * Hd + u0 + (r >> 2);
            float2 v = *(const float2*)&W[(size_t)grow * Hd + kb + (areg >> 1) * 8];
            h8[areg * 2 + 0] = __float2half_rn(v.x);
            h8[areg * 2 + 1] = __float2half_rn(v.y);
        }
        *(uint4*)&sW[(size_t)idx * 8] = *(uint4*)h8;
    }

    // ---- prologue B: pack initial state (grid-strided) ----
    for (int i = cta * NTHR + tid; i < (NL + 1) * Hd * Bz; i += NCTA * NTHR) {
        int u = (i & 32767) >> 6, b = i & 63;
        if (i < Hd * Bz)
            g_Xin[0][0][xoff(u, b)] = __float2half_rn(y[b * Hd + u]);
        else {
            int l = (i >> 15) - 1;
            g_Hrec[0][l][xoff(u, b)] =
                __float2half_rn(h0[(size_t)l * Bz * Hd + b * Hd + u]);
        }
    }

    // epilogue mapping: thread -> (unit j, batch c)
    const int j = tid >> 6;
    const int c = tid & 63;
    const int u = u0 + j;
    const int xo = xoff(u, c);

    float cst[NL];
#pragma unroll
    for (int l = 0; l < NL; l++)
        cst[l] = c0[(size_t)l * Bz * Hd + c * Hd + u];

    float bias[NL][4];
#pragma unroll
    for (int l = 0; l < NL; l++)
#pragma unroll
        for (int g = 0; g < 4; g++)
            bias[l][g] = bih[l * 4 * Hd + g * Hd + u] + bhh[l * 4 * Hd + g * Hd + u];

    int T = Tmax;
    if (seqp) { int tv = *seqp; if (tv > 0 && tv <= Tmax) T = tv; }
    const int R = NL * T;

    // ---- prologue grid barrier ----
    __syncthreads();
    if (tid == 0) {
        arrive_release(&g_bar);
        wait_ge(&g_bar, NCTA);
    }
    __syncthreads();

    // warp roles
    const int kq  = w & 3;          // K quadrant (8 ktiles per half)
    const int nt0 = (w >> 2) * 4;   // first ntile of this warp's N half
    const int kt0 = kq * 8;         // plane-local first ktile
    const uint4* sA0 = (const uint4*)sW;

    uint2 bb[8][4];
    uint4 aX[8];
    float acc[4][4];
#pragma unroll
    for (int n = 0; n < 4; n++)
#pragma unroll
        for (int q = 0; q < 4; q++) acc[n][q] = 0.f;

    // Hrec half for round 0 (t=0, l=0, p=0)
    load_frags(bb, (const uint2*)&g_Hrec[0][0][0], kt0, nt0, lane);
    mma_frags(acc, sA0 + (0 * 64 + 32 + kt0) * 32 + lane, bb);
    // preload Xin A-frags for round 0
    load_afrags(aX, sA0 + (0 * 64 + kt0) * 32 + lane);

    for (int r = 0; r < R; r++) {
        const int t = r >> 2, l = r & 3, p = t & 1;

        // wait(r-1): Xin plane for round r ready (prologue barrier covers r=0)
        if (r > 0) {
            if (tid == 0) wait_ge(&g_bar, (unsigned)(r + 1) * NCTA);
            __syncthreads();
        }

        // Xin half of round r (critical path; A-frags already in registers)
        load_frags(bb, (const uint2*)&g_Xin[p][l][0], kt0, nt0, lane);
        mma_frags_reg(acc, aX, bb);

        // cross-warp K reduction (4-way) via smem
        {
            int gid = lane >> 2, tig = lane & 3;
#pragma unroll
            for (int n = 0; n < 4; n++) {
                int col = (nt0 + n) * 8 + tig * 2;
                *(float2*)&red[(kq * 16 + gid)     * RSTRIDE + col] =
                    make_float2(acc[n][0], acc[n][1]);
                *(float2*)&red[(kq * 16 + gid + 8) * RSTRIDE + col] =
                    make_float2(acc[n][2], acc[n][3]);
            }
        }
        __syncthreads();

        // early Hrec(r+1) fragment loads — latency hides under epilogue
        const int r2 = r + 1, l2 = r2 & 3, p2 = (r2 >> 2) & 1;
        if (r2 < R)
            load_frags(bb, (const uint2*)&g_Hrec[p2][l2][0], kt0, nt0, lane);

        float s0 = 0.f, s1 = 0.f, s2 = 0.f, s3 = 0.f;
#pragma unroll
        for (int kk = 0; kk < 4; kk++) {
            const float* rw = &red[(kk * 16 + j * 4) * RSTRIDE + c];
            s0 += rw[0];
            s1 += rw[RSTRIDE];
            s2 += rw[2 * RSTRIDE];
            s3 += rw[3 * RSTRIDE];
        }

        float iG = sigm(s0 + bias[l][0]);
        float fG = sigm(s1 + bias[l][1]);
        float gG = tanhfast(s2 + bias[l][2]);
        float oG = sigm(s3 + bias[l][3]);
        float cn = fG * cst[l] + iG * gG;
        cst[l] = cn;
        float hn = oG * tanhfast(cn);

        // publish h (single fp16): next-layer input slot + own recurrent slot
        {
            unsigned short hb = __half_as_ushort(__float2half_rn(hn));
            __half* xdst = (l < NL - 1) ? &g_Xin[p][l + 1][0] : &g_Xin[p ^ 1][0][0];
            __stcg((unsigned short*)&xdst[xo], hb);
            __stcg((unsigned short*)&g_Hrec[p ^ 1][l][xo], hb);
        }
        if (l == NL - 1)
            out[((size_t)c * T + t) * Hd + u] = hn;   // out[b][t][u]

        // arrive(r): syncthreads collects publishes; release-red orders them.
        __syncthreads();           // also guards red reuse
        if (tid == 0) arrive_release(&g_bar);

        // Hrec MMAs for round r+1 (fragments already in registers)
        if (r2 < R) {
#pragma unroll
            for (int n = 0; n < 4; n++)
#pragma unroll
                for (int q = 0; q < 4; q++) acc[n][q] = 0.f;
            mma_frags(acc, sA0 + (l2 * 64 + 32 + kt0) * 32 + lane, bb);
            // preload Xin A-frags for round r+1 (before the wait)
            load_afrags(aX, sA0 + (l2 * 64 + kt0) * 32 + lane);
        }
    }

    // self-reset barrier for next graph replay (deterministic state)
    if (cta == 0 && tid == 0) {
        wait_ge(&g_bar, (unsigned)(R + 1) * NCTA);
        *(volatile unsigned*)&g_bar = 0u;
    }
}

extern "C" void kernel_launch(void* const* d_in, const int* in_sizes, int n_in,
                              void* d_out, int out_size) {
    const float* y   = (const float*)d_in[0];
    const float* h0  = (const float*)d_in[1];
    const float* c0  = (const float*)d_in[2];
    const float* Wih = (const float*)d_in[3];
    const float* Whh = (const float*)d_in[4];
    const float* bih = (const float*)d_in[5];
    const float* bhh = (const float*)d_in[6];
    const int*   sl  = (n_in >= 8) ? (const int*)d_in[7] : nullptr;
    float* out = (float*)d_out;
    (void)in_sizes; (void)out_size;

    cudaFuncSetAttribute(lstm_all, cudaFuncAttributeMaxDynamicSharedMemorySize, SMEM_TOT);
    lstm_all<<<NCTA, NTHR, SMEM_TOT>>>(y, h0, c0, Wih, Whh, bih, bhh, sl, out);
}

// round 14
// speedup vs baseline: 1.4016x; 1.0300x over previous
#include <cuda_runtime.h>
#include <cuda_fp16.h>
#include <stdint.h>

// Problem constants (fixed by dataset)
#define NL    4
#define Bz    64
#define Hd    512
#define Tmax  256
#define NCTA  128
#define NTHR  256

#define RSTRIDE 66                       // padded row stride for reduction buf
#define SMEM_W   (4*64*32*16)            // 131072 B: A-fragments, 4 layers x 64 ktiles
#define SMEM_RED (4*16*RSTRIDE*4)        // 16896 B
#define SMEM_TOT (SMEM_W + SMEM_RED)

// ---------------- persistent device state (no allocation allowed) ----------------
// Activations packed in B-fragment order, single fp16, 8B/lane = {b0,b1}
// plane = [32 ktiles][8 ntiles][32 lanes][4 halves] = 32768 halves
__device__ __align__(16) __half g_Xin [2][NL][32768];  // input to layer l, parity p
__device__ __align__(16) __half g_Hrec[2][NL][32768];  // recurrent h of layer l, parity p
__device__ unsigned g_bar;                             // monotonic; self-reset at end

// fast-math activations (MUFU-based, ~1e-6 rel err)
__device__ __forceinline__ float sigm(float x) {
    return __fdividef(1.0f, 1.0f + __expf(-x));
}
__device__ __forceinline__ float tanhfast(float x) {
    return __fdividef(2.0f, 1.0f + __expf(-2.0f * x)) - 1.0f;
}

// release-ordered arrive: orders all prior stores (collected by __syncthreads)
// before the counter increment becomes visible.
__device__ __forceinline__ void arrive_release(unsigned* bar) {
    asm volatile("red.release.gpu.global.add.u32 [%0], 1;" :: "l"(bar) : "memory");
}

// throttled spin: a few hard polls, then back off so 128 pollers don't
// saturate the barrier's L2 line and delay the arriving atomics.
__device__ __forceinline__ void wait_ge(volatile unsigned* vb, unsigned target) {
    int spins = 0;
    while (*vb < target) {
        if (++spins > 4) __nanosleep(32);
    }
}

// offset of X element (k,n) inside a packed plane (single fp16)
__device__ __forceinline__ int xoff(int k, int n) {
    int kt = k >> 4, kr = k & 15, nt = n >> 3, nc = n & 7;
    int lane = nc * 4 + ((kr >> 1) & 3);
    return ((kt * 8 + nt) * 32 + lane) * 4 + ((kr >> 3) * 2 + (kr & 1));
}

__device__ __forceinline__ void mma16816(float* c,
                                         unsigned a0, unsigned a1, unsigned a2, unsigned a3,
                                         unsigned b0, unsigned b1) {
    asm volatile(
        "mma.sync.aligned.m16n8k16.row.col.f32.f16.f16.f32 "
        "{%0,%1,%2,%3}, {%4,%5,%6,%7}, {%8,%9}, {%0,%1,%2,%3};\n"
        : "+f"(c[0]), "+f"(c[1]), "+f"(c[2]), "+f"(c[3])
        : "r"(a0), "r"(a1), "r"(a2), "r"(a3), "r"(b0), "r"(b1));
}

// load 8 ktiles x 4 ntiles of B fragments (32 LDG.64, max MLP)
__device__ __forceinline__ void load_frags(uint2 bb[8][4], const uint2* __restrict__ Bp,
                                           int kt0, int nt0, int lane) {
#pragma unroll
    for (int q = 0; q < 8; q++)
#pragma unroll
        for (int n = 0; n < 4; n++)
            bb[q][n] = __ldcg(Bp + (((kt0 + q) * 8 + nt0 + n) * 32 + lane));
}

// preload 8 A-fragments (smem -> registers)
__device__ __forceinline__ void load_afrags(uint4 a[8], const uint4* __restrict__ sA) {
#pragma unroll
    for (int q = 0; q < 8; q++) a[q] = sA[q * 32];
}

// 32 MMAs from preloaded register A-fragments
__device__ __forceinline__ void mma_frags_reg(float acc[4][4], const uint4 a[8],
                                              uint2 bb[8][4]) {
#pragma unroll
    for (int q = 0; q < 8; q++)
#pragma unroll
        for (int n = 0; n < 4; n++)
            mma16816(acc[n], a[q].x, a[q].y, a[q].z, a[q].w, bb[q][n].x, bb[q][n].y);
}

// 32 MMAs reading A-fragments from smem (off-critical-path half)
__device__ __forceinline__ void mma_frags(float acc[4][4], const uint4* __restrict__ sA,
                                          uint2 bb[8][4]) {
#pragma unroll
    for (int q = 0; q < 8; q++) {
        uint4 a = sA[q * 32];
#pragma unroll
        for (int n = 0; n < 4; n++)
            mma16816(acc[n], a.x, a.y, a.z, a.w, bb[q][n].x, bb[q][n].y);
    }
}

// ---------------- single persistent kernel ----------------
// CTA owns 16 gate rows (4 units x 4 gates). Warp w: kquad = w&3 (8 ktiles per
// half), nhalf = w>>2 (4 ntiles). Critical path per round carries ONLY the
// Xin-destination publish; Hrec-plane and out stores are deferred into the
// shadow region after arrive (ordered by the NEXT round's release, which all
// readers' waits cover with >= 1 full round of slack).
__global__ void __launch_bounds__(NTHR, 1) lstm_all(
    const float* __restrict__ y,
    const float* __restrict__ h0,
    const float* __restrict__ c0,
    const float* __restrict__ Wih,
    const float* __restrict__ Whh,
    const float* __restrict__ bih,
    const float* __restrict__ bhh,
    const int*   __restrict__ seqp,
    float*       __restrict__ out)
{
    extern __shared__ char sm[];
    __half* sW  = (__half*)sm;            // [4][64][32] uint4 A-fragments
    float*  red = (float*)(sm + SMEM_W);  // [4 kquads][16 rows][RSTRIDE]

    const int tid  = threadIdx.x;
    const int cta  = blockIdx.x;
    const int w    = tid >> 5;
    const int lane = tid & 31;
    const int u0   = cta * 4;

    // ---- prologue A: pack this CTA's weights straight into smem (fp16 frags) ----
#pragma unroll 4
    for (int i = 0; i < 32; i++) {
        int idx = i * NTHR + tid;                 // 0..8191 = ((l*64+kt)*32+ln)
        int ln = idx & 31, kt = (idx >> 5) & 63, l = idx >> 11;
        const float* W = ((kt < 32) ? Wih : Whh) + (size_t)l * 4 * Hd * Hd;
        int kb = (kt & 31) * 16 + (ln & 3) * 2;
        __half h8[8];
#pragma unroll
        for (int areg = 0; areg < 4; areg++) {
            int r = (ln >> 2) + (areg & 1) * 8;   // A row 0..15
            int grow = (r & 3) * Hd + u0 + (r >> 2);
            float2 v = *(const float2*)&W[(size_t)grow * Hd + kb + (areg >> 1) * 8];
            h8[areg * 2 + 0] = __float2half_rn(v.x);
            h8[areg * 2 + 1] = __float2half_rn(v.y);
        }
        *(uint4*)&sW[(size_t)idx * 8] = *(uint4*)h8;
    }

    // ---- prologue B: pack initial state (grid-strided) ----
    for (int i = cta * NTHR + tid; i < (NL + 1) * Hd * Bz; i += NCTA * NTHR) {
        int u = (i & 32767) >> 6, b = i & 63;
        if (i < Hd * Bz)
            g_Xin[0][0][xoff(u, b)] = __float2half_rn(y[b * Hd + u]);
        else {
            int l = (i >> 15) - 1;
            g_Hrec[0][l][xoff(u, b)] =
                __float2half_rn(h0[(size_t)l * Bz * Hd + b * Hd + u]);
        }
    }

    // epilogue mapping: thread -> (unit j, batch c)
    const int j = tid >> 6;
    const int c = tid & 63;
    const int u = u0 + j;
    const int xo = xoff(u, c);

    float cst[NL];
#pragma unroll
    for (int l = 0; l < NL; l++)
        cst[l] = c0[(size_t)l * Bz * Hd + c * Hd + u];

    float bias[NL][4];
#pragma unroll
    for (int l = 0; l < NL; l++)
#pragma unroll
        for (int g = 0; g < 4; g++)
            bias[l][g] = bih[l * 4 * Hd + g * Hd + u] + bhh[l * 4 * Hd + g * Hd + u];

    int T = Tmax;
    if (seqp) { int tv = *seqp; if (tv > 0 && tv <= Tmax) T = tv; }
    const int R = NL * T;

    // ---- prologue grid barrier ----
    __syncthreads();
    if (tid == 0) {
        arrive_release(&g_bar);
        wait_ge(&g_bar, NCTA);
    }
    __syncthreads();

    // warp roles
    const int kq  = w & 3;          // K quadrant (8 ktiles per half)
    const int nt0 = (w >> 2) * 4;   // first ntile of this warp's N half
    const int kt0 = kq * 8;         // plane-local first ktile
    const uint4* sA0 = (const uint4*)sW;

    uint2 bb[8][4];
    uint4 aX[8];
    float acc[4][4];
#pragma unroll
    for (int n = 0; n < 4; n++)
#pragma unroll
        for (int q = 0; q < 4; q++) acc[n][q] = 0.f;

    // Hrec half for round 0 (t=0, l=0, p=0)
    load_frags(bb, (const uint2*)&g_Hrec[0][0][0], kt0, nt0, lane);
    mma_frags(acc, sA0 + (0 * 64 + 32 + kt0) * 32 + lane, bb);
    // preload Xin A-frags for round 0
    load_afrags(aX, sA0 + (0 * 64 + kt0) * 32 + lane);

    for (int r = 0; r < R; r++) {
        const int t = r >> 2, l = r & 3, p = t & 1;

        // wait(r-1): Xin plane for round r ready (prologue barrier covers r=0)
        if (r > 0) {
            if (tid == 0) wait_ge(&g_bar, (unsigned)(r + 1) * NCTA);
            __syncthreads();
        }

        // Xin half of round r (critical path; A-frags already in registers)
        load_frags(bb, (const uint2*)&g_Xin[p][l][0], kt0, nt0, lane);
        mma_frags_reg(acc, aX, bb);

        // cross-warp K reduction (4-way) via smem
        {
            int gid = lane >> 2, tig = lane & 3;
#pragma unroll
            for (int n = 0; n < 4; n++) {
                int col = (nt0 + n) * 8 + tig * 2;
                *(float2*)&red[(kq * 16 + gid)     * RSTRIDE + col] =
                    make_float2(acc[n][0], acc[n][1]);
                *(float2*)&red[(kq * 16 + gid + 8) * RSTRIDE + col] =
                    make_float2(acc[n][2], acc[n][3]);
            }
        }
        __syncthreads();

        // early Hrec(r+1) fragment loads — latency hides under epilogue
        const int r2 = r + 1, l2 = r2 & 3, p2 = (r2 >> 2) & 1;
        if (r2 < R)
            load_frags(bb, (const uint2*)&g_Hrec[p2][l2][0], kt0, nt0, lane);

        float s0 = 0.f, s1 = 0.f, s2 = 0.f, s3 = 0.f;
#pragma unroll
        for (int kk = 0; kk < 4; kk++) {
            const float* rw = &red[(kk * 16 + j * 4) * RSTRIDE + c];
            s0 += rw[0];
            s1 += rw[RSTRIDE];
            s2 += rw[2 * RSTRIDE];
            s3 += rw[3 * RSTRIDE];
        }

        float iG = sigm(s0 + bias[l][0]);
        float fG = sigm(s1 + bias[l][1]);
        float gG = tanhfast(s2 + bias[l][2]);
        float oG = sigm(s3 + bias[l][3]);
        float cn = fG * cst[l] + iG * gG;
        cst[l] = cn;
        float hn = oG * tanhfast(cn);

        // critical-path publish: ONLY the next-round Xin destination
        unsigned short hb = __half_as_ushort(__float2half_rn(hn));
        {
            __half* xdst = (l < NL - 1) ? &g_Xin[p][l + 1][0] : &g_Xin[p ^ 1][0][0];
            __stcg((unsigned short*)&xdst[xo], hb);
        }

        // arrive(r): syncthreads collects the Xin publishes; release-red orders
        // them before the counter increment.
        __syncthreads();           // also guards red reuse
        if (tid == 0) arrive_release(&g_bar);

        // ---- shadow region (off the critical path) ----
        // deferred publishes: Hrec plane (first read at round r+4, ordered by
        // our arrive(r+1)) and the output tensor (read only after kernel end).
        __stcg((unsigned short*)&g_Hrec[p ^ 1][l][xo], hb);
        if (l == NL - 1)
            out[((size_t)c * T + t) * Hd + u] = hn;   // out[b][t][u]

        // Hrec MMAs for round r+1 (fragments already in registers)
        if (r2 < R) {
#pragma unroll
            for (int n = 0; n < 4; n++)
#pragma unroll
                for (int q = 0; q < 4; q++) acc[n][q] = 0.f;
            mma_frags(acc, sA0 + (l2 * 64 + 32 + kt0) * 32 + lane, bb);
            // preload Xin A-frags for round r+1 (before the wait)
            load_afrags(aX, sA0 + (l2 * 64 + kt0) * 32 + lane);
        }
    }

    // self-reset barrier for next graph replay (deterministic state)
    if (cta == 0 && tid == 0) {
        wait_ge(&g_bar, (unsigned)(R + 1) * NCTA);
        *(volatile unsigned*)&g_bar = 0u;
    }
}

extern "C" void kernel_launch(void* const* d_in, const int* in_sizes, int n_in,
                              void* d_out, int out_size) {
    const float* y   = (const float*)d_in[0];
    const float* h0  = (const float*)d_in[1];
    const float* c0  = (const float*)d_in[2];
    const float* Wih = (const float*)d_in[3];
    const float* Whh = (const float*)d_in[4];
    const float* bih = (const float*)d_in[5];
    const float* bhh = (const float*)d_in[6];
    const int*   sl  = (n_in >= 8) ? (const int*)d_in[7] : nullptr;
    float* out = (float*)d_out;
    (void)in_sizes; (void)out_size;

    cudaFuncSetAttribute(lstm_all, cudaFuncAttributeMaxDynamicSharedMemorySize, SMEM_TOT);
    lstm_all<<<NCTA, NTHR, SMEM_TOT>>>(y, h0, c0, Wih, Whh, bih, bhh, sl, out);
}